// round 8
// baseline (speedup 1.0000x reference)
#include <cuda_runtime.h>
#include <cuda_bf16.h>
#include <cstdint>

#define B_  8
#define S_  1024
#define H_  1024
#define NH_ 16
#define HD_ 64
#define MROWS (B_ * S_)

// Scratch: Q, K, V projections and attention output (each 32 MB).
__device__ float g_Q[MROWS * H_];
__device__ float g_K[MROWS * H_];
__device__ float g_V[MROWS * H_];
__device__ float g_A[MROWS * H_];

__device__ __forceinline__ uint32_t smem_u32(const void* p) {
    uint32_t a;
    asm("{ .reg .u64 t; cvta.to.shared.u64 t, %1; cvt.u32.u64 %0, t; }"
        : "=r"(a) : "l"(p));
    return a;
}

#define LDMX4(r0, r1, r2, r3, addr) \
    asm volatile("ldmatrix.sync.aligned.m8n8.x4.shared.b16 {%0,%1,%2,%3}, [%4];" \
                 : "=r"(r0), "=r"(r1), "=r"(r2), "=r"(r3) : "r"(addr))

#define LDMX4T(r0, r1, r2, r3, addr) \
    asm volatile("ldmatrix.sync.aligned.m8n8.x4.trans.shared.b16 {%0,%1,%2,%3}, [%4];" \
                 : "=r"(r0), "=r"(r1), "=r"(r2), "=r"(r3) : "r"(addr))

#define MMA16816(d, a, b) \
    asm volatile("mma.sync.aligned.m16n8k16.row.col.f32.bf16.bf16.f32 " \
                 "{%0,%1,%2,%3}, {%4,%5,%6,%7}, {%8,%9}, {%0,%1,%2,%3};" \
                 : "+f"((d)[0]), "+f"((d)[1]), "+f"((d)[2]), "+f"((d)[3]) \
                 : "r"((a)[0]), "r"((a)[1]), "r"((a)[2]), "r"((a)[3]), \
                   "r"((b)[0]), "r"((b)[1]))

__device__ __forceinline__ uint32_t pack_hi(float x, float y) {
    __nv_bfloat162 h = __float22bfloat162_rn(make_float2(x, y));
    return *(uint32_t*)&h;
}
__device__ __forceinline__ uint32_t pack_lo(float x, float y, uint32_t hi) {
    __nv_bfloat162 h = *(__nv_bfloat162*)&hi;
    __nv_bfloat162 l = __float22bfloat162_rn(make_float2(
        x - __bfloat162float(h.x), y - __bfloat162float(h.y)));
    return *(uint32_t*)&l;
}

// ===========================================================================
// bf16 mma.sync split-precision GEMM body. Double-buffered; staging of the
// NEXT chunk sits in the same barrier interval as compute of the current one
// (different buffers), so warp skew overlaps CVT/STS with HMMA.
// One __syncthreads per chunk.
// ===========================================================================
#define LDSROW 40
#define GOP_ELEMS   (128 * LDSROW)
#define GSTAGE_ELEMS (4 * GOP_ELEMS)
#define GSTAGE_BYTES (GSTAGE_ELEMS * 2)
#define GEMM_SMEM    (2 * GSTAGE_BYTES)     // 81920

__device__ __forceinline__ void gemm_stage(
    __nv_bfloat16* st, const int* gRow, const int* gC4,
    const float4* ra, const float4* rw)
{
#pragma unroll
    for (int i = 0; i < 4; i++) {
        const int off = gRow[i] * LDSROW + gC4[i] * 4;
        float4 a4 = ra[i], w4 = rw[i];
        uint32_t ah01 = pack_hi(a4.x, a4.y), ah23 = pack_hi(a4.z, a4.w);
        *(uint32_t*)(st + off)     = ah01;
        *(uint32_t*)(st + off + 2) = ah23;
        *(uint32_t*)(st + GOP_ELEMS + off)     = pack_lo(a4.x, a4.y, ah01);
        *(uint32_t*)(st + GOP_ELEMS + off + 2) = pack_lo(a4.z, a4.w, ah23);

        uint32_t wh01 = pack_hi(w4.x, w4.y), wh23 = pack_hi(w4.z, w4.w);
        *(uint32_t*)(st + 2 * GOP_ELEMS + off)     = wh01;
        *(uint32_t*)(st + 2 * GOP_ELEMS + off + 2) = wh23;
        *(uint32_t*)(st + 3 * GOP_ELEMS + off)     = pack_lo(w4.x, w4.y, wh01);
        *(uint32_t*)(st + 3 * GOP_ELEMS + off + 2) = pack_lo(w4.z, w4.w, wh23);
    }
}

__device__ __forceinline__ void gemm_body(
    const float* __restrict__ A, const float* __restrict__ W,
    const float* __restrict__ bias, float* __restrict__ C,
    __nv_bfloat16* gsm, int bm0, int bn0)
{
    const int tid  = threadIdx.x;
    const int wid  = tid >> 5;
    const int lane = tid & 31;
    const int wm   = wid & 1;
    const int wn   = wid >> 1;

    const uint32_t ubase = smem_u32(gsm);
    const uint32_t aLOff = (uint32_t)((wm * 64 + (lane & 15)) * (LDSROW * 2) + (lane >> 4) * 16);
    const uint32_t bLOff = (uint32_t)((wn * 32 + ((lane >> 4) & 1) * 8 + (lane & 7)) * (LDSROW * 2)
                                      + ((lane >> 3) & 1) * 16);

    int gRow[4], gC4[4];
#pragma unroll
    for (int i = 0; i < 4; i++) { int s = tid + i * 256; gRow[i] = s >> 3; gC4[i] = s & 7; }

    float acc[4][4][4];
#pragma unroll
    for (int mi = 0; mi < 4; mi++)
#pragma unroll
        for (int nj = 0; nj < 4; nj++)
#pragma unroll
            for (int e = 0; e < 4; e++) acc[mi][nj][e] = 0.f;

    const float* Ab = A + (size_t)bm0 * H_;
    const float* Wb = W + (size_t)bn0 * H_;

    float4 ra[4], rw[4];
    // prologue: chunk 0 -> buf0, chunk 1 -> regs
#pragma unroll
    for (int i = 0; i < 4; i++) {
        ra[i] = *(const float4*)(Ab + (size_t)gRow[i] * H_ + gC4[i] * 4);
        rw[i] = *(const float4*)(Wb + (size_t)gRow[i] * H_ + gC4[i] * 4);
    }
    gemm_stage(gsm, gRow, gC4, ra, rw);
#pragma unroll
    for (int i = 0; i < 4; i++) {
        ra[i] = *(const float4*)(Ab + (size_t)gRow[i] * H_ + 32 + gC4[i] * 4);
        rw[i] = *(const float4*)(Wb + (size_t)gRow[i] * H_ + 32 + gC4[i] * 4);
    }
    __syncthreads();

    for (int c = 0; c < 32; c++) {
        const int sel = c & 1;
        // stage chunk c+1 into the other buffer (overlaps with compute below)
        if (c < 31)
            gemm_stage(gsm + (sel ^ 1) * GSTAGE_ELEMS, gRow, gC4, ra, rw);
        if (c < 30) {
            const int k0 = (c + 2) * 32;
#pragma unroll
            for (int i = 0; i < 4; i++) {
                ra[i] = *(const float4*)(Ab + (size_t)gRow[i] * H_ + k0 + gC4[i] * 4);
                rw[i] = *(const float4*)(Wb + (size_t)gRow[i] * H_ + k0 + gC4[i] * 4);
            }
        }

        const uint32_t ub  = ubase + (uint32_t)sel * GSTAGE_BYTES;
        const uint32_t bAh = ub;
        const uint32_t bAl = ub + GOP_ELEMS * 2;
        const uint32_t bWh = ub + 2 * GOP_ELEMS * 2;
        const uint32_t bWl = ub + 3 * GOP_ELEMS * 2;
#pragma unroll
        for (int ks = 0; ks < 2; ks++) {
            const uint32_t kb = (uint32_t)(ks * 32);
            uint32_t ah[4][4], al[4][4];
#pragma unroll
            for (int mi = 0; mi < 4; mi++) {
                const uint32_t rowb = (uint32_t)(mi * 16 * LDSROW * 2) + aLOff + kb;
                LDMX4(ah[mi][0], ah[mi][1], ah[mi][2], ah[mi][3], bAh + rowb);
                LDMX4(al[mi][0], al[mi][1], al[mi][2], al[mi][3], bAl + rowb);
            }
            uint32_t bh[4][2], bl[4][2];
#pragma unroll
            for (int pr = 0; pr < 2; pr++) {
                const uint32_t rowb = (uint32_t)(pr * 16 * LDSROW * 2) + bLOff + kb;
                LDMX4(bh[pr * 2][0], bh[pr * 2][1], bh[pr * 2 + 1][0], bh[pr * 2 + 1][1], bWh + rowb);
                LDMX4(bl[pr * 2][0], bl[pr * 2][1], bl[pr * 2 + 1][0], bl[pr * 2 + 1][1], bWl + rowb);
            }
#pragma unroll
            for (int mi = 0; mi < 4; mi++)
#pragma unroll
                for (int nj = 0; nj < 4; nj++) {
                    MMA16816(acc[mi][nj], ah[mi], bh[nj]);
                    MMA16816(acc[mi][nj], al[mi], bh[nj]);
                    MMA16816(acc[mi][nj], ah[mi], bl[nj]);
                }
        }
        __syncthreads();
    }

#pragma unroll
    for (int mi = 0; mi < 4; mi++) {
        const int r0 = bm0 + wm * 64 + mi * 16 + (lane >> 2);
#pragma unroll
        for (int nj = 0; nj < 4; nj++) {
            const int col = bn0 + wn * 32 + nj * 8 + (lane & 3) * 2;
            const float b0 = bias[col], b1 = bias[col + 1];
            float2 o0 = make_float2(acc[mi][nj][0] + b0, acc[mi][nj][1] + b1);
            float2 o1 = make_float2(acc[mi][nj][2] + b0, acc[mi][nj][3] + b1);
            *(float2*)(C + (size_t)r0 * H_ + col)       = o0;
            *(float2*)(C + (size_t)(r0 + 8) * H_ + col) = o1;
        }
    }
}

__global__ __launch_bounds__(256, 1)
void gemm_tc(const float* __restrict__ A, const float* __restrict__ W,
             const float* __restrict__ bias, float* __restrict__ C)
{
    extern __shared__ __nv_bfloat16 gsm[];
    gemm_body(A, W, bias, C, gsm, blockIdx.y * 128, blockIdx.x * 128);
}

// Fused Q/K/V projections: one launch, z selects the operand set.
__global__ __launch_bounds__(256, 1)
void qkv_tc(const float* __restrict__ q, const float* __restrict__ k,
            const float* __restrict__ v,
            const float* __restrict__ Wq, const float* __restrict__ bq,
            const float* __restrict__ Wk, const float* __restrict__ bk,
            const float* __restrict__ Wv, const float* __restrict__ bv,
            float* __restrict__ Qo, float* __restrict__ Ko, float* __restrict__ Vo)
{
    extern __shared__ __nv_bfloat16 gsm[];
    const float *A, *W, *bias;
    float* C;
    if (blockIdx.z == 0)      { A = q; W = Wq; bias = bq; C = Qo; }
    else if (blockIdx.z == 1) { A = k; W = Wk; bias = bk; C = Ko; }
    else                      { A = v; W = Wv; bias = bv; C = Vo; }
    gemm_body(A, W, bias, C, gsm, blockIdx.y * 128, blockIdx.x * 128);
}

// ===========================================================================
// Tensor-core flash attention (unchanged from R7, known-good).
// BQ=128 (8 warps), double-buffered K/V with register prefetch.
// ===========================================================================
#define AT_ROW 72
#define AT_OP_ELEMS (64 * AT_ROW)
#define AT_STAGE_ELEMS (4 * AT_OP_ELEMS)
#define AT_STAGE_BYTES (AT_STAGE_ELEMS * 2)
#define ATTN_SMEM (2 * AT_STAGE_BYTES)

__device__ __forceinline__ void attn_load_kv(
    const float* Kp, const float* Vp, int tid, float4* kn, float4* vn)
{
#pragma unroll
    for (int i = 0; i < 4; i++) {
        const int slot = tid + i * 256;
        const int r  = slot >> 4;
        const int c4 = slot & 15;
        kn[i] = *(const float4*)(Kp + (size_t)r * H_ + c4 * 4);
        vn[i] = *(const float4*)(Vp + (size_t)r * H_ + c4 * 4);
    }
}

__device__ __forceinline__ void attn_stage_kv(
    __nv_bfloat16* st, int tid, const float4* kn, const float4* vn)
{
#pragma unroll
    for (int i = 0; i < 4; i++) {
        const int slot = tid + i * 256;
        const int r  = slot >> 4;
        const int c4 = slot & 15;
        const int off = r * AT_ROW + c4 * 4;
        float4 kv = kn[i];
        uint32_t kh01 = pack_hi(kv.x, kv.y), kh23 = pack_hi(kv.z, kv.w);
        *(uint32_t*)(st + off)     = kh01;
        *(uint32_t*)(st + off + 2) = kh23;
        *(uint32_t*)(st + AT_OP_ELEMS + off)     = pack_lo(kv.x, kv.y, kh01);
        *(uint32_t*)(st + AT_OP_ELEMS + off + 2) = pack_lo(kv.z, kv.w, kh23);
        float4 vv = vn[i];
        uint32_t vh01 = pack_hi(vv.x, vv.y), vh23 = pack_hi(vv.z, vv.w);
        *(uint32_t*)(st + 2 * AT_OP_ELEMS + off)     = vh01;
        *(uint32_t*)(st + 2 * AT_OP_ELEMS + off + 2) = vh23;
        *(uint32_t*)(st + 3 * AT_OP_ELEMS + off)     = pack_lo(vv.x, vv.y, vh01);
        *(uint32_t*)(st + 3 * AT_OP_ELEMS + off + 2) = pack_lo(vv.z, vv.w, vh23);
    }
}

__global__ __launch_bounds__(256, 1)
void attn_tc(const float* __restrict__ Qm, const float* __restrict__ Km,
             const float* __restrict__ Vm, const int* __restrict__ mask,
             float* __restrict__ O)
{
    extern __shared__ __nv_bfloat16 asmem[];
    __shared__ uint32_t mbits[2][2];

    const int tid  = threadIdx.x;
    const int wid  = tid >> 5;
    const int lane = tid & 31;
    const int qt = blockIdx.x;
    const int h  = blockIdx.y;
    const int b  = blockIdx.z;

    const uint32_t ubase = smem_u32(asmem);

    const int r0 = wid * 16 + (lane >> 2);
    const float* Qb = Qm + ((size_t)(b * S_ + qt * 128)) * H_ + h * HD_;
    uint32_t qh[4][4], ql[4][4];
#pragma unroll
    for (int ks = 0; ks < 4; ks++) {
        const int kb = ks * 16 + (lane & 3) * 2;
        float2 v0 = *(const float2*)(Qb + (size_t)r0 * H_ + kb);
        float2 v1 = *(const float2*)(Qb + (size_t)(r0 + 8) * H_ + kb);
        float2 v2 = *(const float2*)(Qb + (size_t)r0 * H_ + kb + 8);
        float2 v3 = *(const float2*)(Qb + (size_t)(r0 + 8) * H_ + kb + 8);
        qh[ks][0] = pack_hi(v0.x, v0.y);  ql[ks][0] = pack_lo(v0.x, v0.y, qh[ks][0]);
        qh[ks][1] = pack_hi(v1.x, v1.y);  ql[ks][1] = pack_lo(v1.x, v1.y, qh[ks][1]);
        qh[ks][2] = pack_hi(v2.x, v2.y);  ql[ks][2] = pack_lo(v2.x, v2.y, qh[ks][2]);
        qh[ks][3] = pack_hi(v3.x, v3.y);  ql[ks][3] = pack_lo(v3.x, v3.y, qh[ks][3]);
    }

    float oacc[8][4];
#pragma unroll
    for (int nj = 0; nj < 8; nj++)
#pragma unroll
        for (int e = 0; e < 4; e++) oacc[nj][e] = 0.f;
    float m0 = -1e30f, m1 = -1e30f, l0 = 0.f, l1 = 0.f;

    const float* Kb = Km + ((size_t)b * S_) * H_ + h * HD_;
    const float* Vb = Vm + ((size_t)b * S_) * H_ + h * HD_;

    float4 kn[4], vn[4];
    attn_load_kv(Kb, Vb, tid, kn, vn);
    attn_stage_kv(asmem, tid, kn, vn);
    int mv0 = 0, mv1 = 0;
    if (wid == 0) {
        mv0 = mask[(size_t)b * S_ + lane];
        mv1 = mask[(size_t)b * S_ + 32 + lane];
        unsigned b0v = __ballot_sync(0xffffffffu, mv0 != 0);
        unsigned b1v = __ballot_sync(0xffffffffu, mv1 != 0);
        if (lane == 0) { mbits[0][0] = b0v; mbits[0][1] = b1v; }
    }

    for (int kt = 0; kt < 16; kt++) {
        const int sel = kt & 1;
        __syncthreads();
        const uint32_t mw0 = mbits[sel][0];
        const uint32_t mw1 = mbits[sel][1];
        const uint32_t ub  = ubase + (uint32_t)sel * AT_STAGE_BYTES;
        const uint32_t bKh = ub;
        const uint32_t bKl = ub + AT_OP_ELEMS * 2;
        const uint32_t bVh = ub + 2 * AT_OP_ELEMS * 2;
        const uint32_t bVl = ub + 3 * AT_OP_ELEMS * 2;

        float sacc[8][4];
#pragma unroll
        for (int nj = 0; nj < 8; nj++)
#pragma unroll
            for (int e = 0; e < 4; e++) sacc[nj][e] = 0.f;

#pragma unroll
        for (int ks = 0; ks < 4; ks++) {
            uint32_t bh[8][2], bl[8][2];
#pragma unroll
            for (int g = 0; g < 4; g++) {
                const uint32_t rowb =
                    (uint32_t)((g * 16 + ((lane >> 4) & 1) * 8 + (lane & 7)) * (AT_ROW * 2)
                               + ks * 32 + ((lane >> 3) & 1) * 16);
                LDMX4(bh[2 * g][0], bh[2 * g][1], bh[2 * g + 1][0], bh[2 * g + 1][1], bKh + rowb);
                LDMX4(bl[2 * g][0], bl[2 * g][1], bl[2 * g + 1][0], bl[2 * g + 1][1], bKl + rowb);
            }
#pragma unroll
            for (int nj = 0; nj < 8; nj++) {
                MMA16816(sacc[nj], qh[ks], bh[nj]);
                MMA16816(sacc[nj], ql[ks], bh[nj]);
                MMA16816(sacc[nj], qh[ks], bl[nj]);
            }
        }

        if (kt < 15) {
            attn_load_kv(Kb + (size_t)(kt + 1) * 64 * H_,
                         Vb + (size_t)(kt + 1) * 64 * H_, tid, kn, vn);
            if (wid == 0) {
                mv0 = mask[(size_t)b * S_ + (kt + 1) * 64 + lane];
                mv1 = mask[(size_t)b * S_ + (kt + 1) * 64 + 32 + lane];
            }
        }

        const int shb = (lane & 3) * 2;
        float mx0 = -1e30f, mx1 = -1e30f;
#pragma unroll
        for (int nj = 0; nj < 8; nj++) {
            const uint32_t w = (nj < 4) ? mw0 : mw1;
            const int sh = (nj & 3) * 8 + shb;
            const bool k0 = (w >> sh) & 1;
            const bool k1 = (w >> (sh + 1)) & 1;
            float s0 = k0 ? -1e30f : sacc[nj][0] * 0.03125f;
            float s1 = k1 ? -1e30f : sacc[nj][1] * 0.03125f;
            float s2 = k0 ? -1e30f : sacc[nj][2] * 0.03125f;
            float s3 = k1 ? -1e30f : sacc[nj][3] * 0.03125f;
            sacc[nj][0] = s0; sacc[nj][1] = s1; sacc[nj][2] = s2; sacc[nj][3] = s3;
            mx0 = fmaxf(mx0, fmaxf(s0, s1));
            mx1 = fmaxf(mx1, fmaxf(s2, s3));
        }
        mx0 = fmaxf(mx0, __shfl_xor_sync(0xffffffffu, mx0, 1));
        mx0 = fmaxf(mx0, __shfl_xor_sync(0xffffffffu, mx0, 2));
        mx1 = fmaxf(mx1, __shfl_xor_sync(0xffffffffu, mx1, 1));
        mx1 = fmaxf(mx1, __shfl_xor_sync(0xffffffffu, mx1, 2));

        const float nm0 = fmaxf(m0, mx0);
        const float nm1 = fmaxf(m1, mx1);
        const float f0 = __expf(m0 - nm0);
        const float f1 = __expf(m1 - nm1);
        m0 = nm0; m1 = nm1;
        l0 *= f0;  l1 *= f1;
#pragma unroll
        for (int nj = 0; nj < 8; nj++) {
            oacc[nj][0] *= f0; oacc[nj][1] *= f0;
            oacc[nj][2] *= f1; oacc[nj][3] *= f1;
        }

        uint32_t pHa[8], pHb[8], pLa[8], pLb[8];
        float ps0 = 0.f, ps1 = 0.f;
#pragma unroll
        for (int nj = 0; nj < 8; nj++) {
            float p0 = __expf(sacc[nj][0] - nm0);
            float p1 = __expf(sacc[nj][1] - nm0);
            float p2 = __expf(sacc[nj][2] - nm1);
            float p3 = __expf(sacc[nj][3] - nm1);
            ps0 += p0 + p1;
            ps1 += p2 + p3;
            pHa[nj] = pack_hi(p0, p1);  pLa[nj] = pack_lo(p0, p1, pHa[nj]);
            pHb[nj] = pack_hi(p2, p3);  pLb[nj] = pack_lo(p2, p3, pHb[nj]);
        }
        l0 += ps0;
        l1 += ps1;

#pragma unroll
        for (int kk = 0; kk < 4; kk++) {
            uint32_t aH[4] = { pHa[2 * kk], pHb[2 * kk], pHa[2 * kk + 1], pHb[2 * kk + 1] };
            uint32_t aL[4] = { pLa[2 * kk], pLb[2 * kk], pLa[2 * kk + 1], pLb[2 * kk + 1] };
#pragma unroll
            for (int njp = 0; njp < 8; njp += 2) {
                const uint32_t rowb =
                    (uint32_t)((kk * 16 + (lane & 15)) * (AT_ROW * 2)
                               + (njp + ((lane >> 4) & 1)) * 16);
                uint32_t vh[2][2], vl[2][2];
                LDMX4T(vh[0][0], vh[0][1], vh[1][0], vh[1][1], bVh + rowb);
                LDMX4T(vl[0][0], vl[0][1], vl[1][0], vl[1][1], bVl + rowb);
                MMA16816(oacc[njp],     aH, vh[0]);
                MMA16816(oacc[njp],     aL, vh[0]);
                MMA16816(oacc[njp],     aH, vl[0]);
                MMA16816(oacc[njp + 1], aH, vh[1]);
                MMA16816(oacc[njp + 1], aL, vh[1]);
                MMA16816(oacc[njp + 1], aH, vl[1]);
            }
        }

        if (kt < 15) {
            attn_stage_kv(asmem + (sel ^ 1) * AT_STAGE_ELEMS, tid, kn, vn);
            if (wid == 0) {
                unsigned b0v = __ballot_sync(0xffffffffu, mv0 != 0);
                unsigned b1v = __ballot_sync(0xffffffffu, mv1 != 0);
                if (lane == 0) { mbits[sel ^ 1][0] = b0v; mbits[sel ^ 1][1] = b1v; }
            }
        }
    }

    l0 += __shfl_xor_sync(0xffffffffu, l0, 1);
    l0 += __shfl_xor_sync(0xffffffffu, l0, 2);
    l1 += __shfl_xor_sync(0xffffffffu, l1, 1);
    l1 += __shfl_xor_sync(0xffffffffu, l1, 2);
    const float rl0 = 1.f / l0;
    const float rl1 = 1.f / l1;

    float* Ob = O + ((size_t)(b * S_ + qt * 128)) * H_ + h * HD_;
#pragma unroll
    for (int nj = 0; nj < 8; nj++) {
        const int colb = nj * 8 + (lane & 3) * 2;
        *(float2*)(Ob + (size_t)r0 * H_ + colb) =
            make_float2(oacc[nj][0] * rl0, oacc[nj][1] * rl0);
        *(float2*)(Ob + (size_t)(r0 + 8) * H_ + colb) =
            make_float2(oacc[nj][2] * rl1, oacc[nj][3] * rl1);
    }
}

// ---------------------------------------------------------------------------
extern "C" void kernel_launch(void* const* d_in, const int* in_sizes, int n_in,
                              void* d_out, int out_size)
{
    const float* query = (const float*)d_in[0];
    const float* key   = (const float*)d_in[1];
    const float* value = (const float*)d_in[2];
    const int*   mask  = (const int*)d_in[3];

    const int wb = (n_in >= 13) ? 5 : 4;
    const float* Wq = (const float*)d_in[wb + 0];
    const float* bq = (const float*)d_in[wb + 1];
    const float* Wk = (const float*)d_in[wb + 2];
    const float* bk = (const float*)d_in[wb + 3];
    const float* Wv = (const float*)d_in[wb + 4];
    const float* bv = (const float*)d_in[wb + 5];
    const float* Wo = (const float*)d_in[wb + 6];
    const float* bo = (const float*)d_in[wb + 7];
    float* out = (float*)d_out;

    float *dQ, *dK, *dV, *dA;
    cudaGetSymbolAddress((void**)&dQ, g_Q);
    cudaGetSymbolAddress((void**)&dK, g_K);
    cudaGetSymbolAddress((void**)&dV, g_V);
    cudaGetSymbolAddress((void**)&dA, g_A);

    cudaFuncSetAttribute(gemm_tc, cudaFuncAttributeMaxDynamicSharedMemorySize, GEMM_SMEM);
    cudaFuncSetAttribute(qkv_tc,  cudaFuncAttributeMaxDynamicSharedMemorySize, GEMM_SMEM);
    cudaFuncSetAttribute(attn_tc, cudaFuncAttributeMaxDynamicSharedMemorySize, ATTN_SMEM);

    dim3 qkvgrid(H_ / 128, MROWS / 128, 3);  // (8, 64, 3)
    qkv_tc<<<qkvgrid, 256, GEMM_SMEM>>>(query, key, value,
                                        Wq, bq, Wk, bk, Wv, bv,
                                        dQ, dK, dV);

    dim3 agrid(S_ / 128, NH_, B_);           // (8, 16, 8)
    attn_tc<<<agrid, 256, ATTN_SMEM>>>(dQ, dK, dV, mask, dA);

    dim3 ggrid(H_ / 128, MROWS / 128);       // (8, 64)
    gemm_tc<<<ggrid, 256, GEMM_SMEM>>>(dA, Wo, bo, out);
}

// round 10
// speedup vs baseline: 1.0840x; 1.0840x over previous
#include <cuda_runtime.h>
#include <cuda_bf16.h>
#include <cstdint>

#define B_  8
#define S_  1024
#define H_  1024
#define NH_ 16
#define HD_ 64
#define MROWS (B_ * S_)

// fp32 scratch (attention path unchanged)
__device__ float g_Q[MROWS * H_];
__device__ float g_K[MROWS * H_];
__device__ float g_V[MROWS * H_];
__device__ float g_A[MROWS * H_];

// bf16 hi/lo pre-converted GEMM operands
__device__ __nv_bfloat16 g_qh[MROWS * H_], g_ql[MROWS * H_];
__device__ __nv_bfloat16 g_kh[MROWS * H_], g_kl[MROWS * H_];
__device__ __nv_bfloat16 g_vh[MROWS * H_], g_vl[MROWS * H_];
__device__ __nv_bfloat16 g_ah[MROWS * H_], g_al[MROWS * H_];
__device__ __nv_bfloat16 g_wqh[H_ * H_], g_wql[H_ * H_];
__device__ __nv_bfloat16 g_wkh[H_ * H_], g_wkl[H_ * H_];
__device__ __nv_bfloat16 g_wvh[H_ * H_], g_wvl[H_ * H_];
__device__ __nv_bfloat16 g_woh[H_ * H_], g_wol[H_ * H_];

__device__ __forceinline__ uint32_t smem_u32(const void* p) {
    uint32_t a;
    asm("{ .reg .u64 t; cvta.to.shared.u64 t, %1; cvt.u32.u64 %0, t; }"
        : "=r"(a) : "l"(p));
    return a;
}

#define LDMX4(r0, r1, r2, r3, addr) \
    asm volatile("ldmatrix.sync.aligned.m8n8.x4.shared.b16 {%0,%1,%2,%3}, [%4];" \
                 : "=r"(r0), "=r"(r1), "=r"(r2), "=r"(r3) : "r"(addr))

#define LDMX4T(r0, r1, r2, r3, addr) \
    asm volatile("ldmatrix.sync.aligned.m8n8.x4.trans.shared.b16 {%0,%1,%2,%3}, [%4];" \
                 : "=r"(r0), "=r"(r1), "=r"(r2), "=r"(r3) : "r"(addr))

#define MMA16816(d, a, b) \
    asm volatile("mma.sync.aligned.m16n8k16.row.col.f32.bf16.bf16.f32 " \
                 "{%0,%1,%2,%3}, {%4,%5,%6,%7}, {%8,%9}, {%0,%1,%2,%3};" \
                 : "+f"((d)[0]), "+f"((d)[1]), "+f"((d)[2]), "+f"((d)[3]) \
                 : "r"((a)[0]), "r"((a)[1]), "r"((a)[2]), "r"((a)[3]), \
                   "r"((b)[0]), "r"((b)[1]))

#define CPA16(dst, src) \
    asm volatile("cp.async.cg.shared.global [%0], [%1], 16;" :: "r"(dst), "l"(src))
#define CP_COMMIT() asm volatile("cp.async.commit_group;")
#define CP_WAIT(n)  asm volatile("cp.async.wait_group %0;" :: "n"(n))

__device__ __forceinline__ uint32_t pack_hi(float x, float y) {
    __nv_bfloat162 h = __float22bfloat162_rn(make_float2(x, y));
    return *(uint32_t*)&h;
}
__device__ __forceinline__ uint32_t pack_lo(float x, float y, uint32_t hi) {
    __nv_bfloat162 h = *(__nv_bfloat162*)&hi;
    __nv_bfloat162 l = __float22bfloat162_rn(make_float2(
        x - __bfloat162float(h.x), y - __bfloat162float(h.y)));
    return *(uint32_t*)&l;
}

// ===========================================================================
// fp32 -> bf16 hi/lo split convert (grid-stride, float4 granularity)
// ===========================================================================
__global__ __launch_bounds__(256)
void conv_hl(const float* __restrict__ src, __nv_bfloat16* __restrict__ hi,
             __nv_bfloat16* __restrict__ lo, int n4)
{
    for (int i = blockIdx.x * blockDim.x + threadIdx.x; i < n4;
         i += gridDim.x * blockDim.x) {
        float4 v = ((const float4*)src)[i];
        uint32_t h0 = pack_hi(v.x, v.y), h1 = pack_hi(v.z, v.w);
        uint32_t l0 = pack_lo(v.x, v.y, h0), l1 = pack_lo(v.z, v.w, h1);
        ((uint2*)hi)[i] = make_uint2(h0, h1);
        ((uint2*)lo)[i] = make_uint2(l0, l1);
    }
}

// ===========================================================================
// Pre-converted bf16 hi/lo GEMM: C[m,n] = sum_k A[m,k]*W[n,k] + bias[n]
// 128x128 tile, BK=64, 2-stage cp.async pipeline, 8 warps (2x4 / 64x32).
// Hot loop is pure cp.async + ldmatrix + HMMA.
// ===========================================================================
#define HLROW     72                    // bf16 per smem row: 64 + 8 pad (144 B)
#define HLTILE_B  (128 * HLROW * 2)     // 18432 B per operand tile
#define HLSTAGE_B (4 * HLTILE_B)        // 73728 B (Ah, Al, Wh, Wl)
#define HLSTAGES  2
#define GEMM_SMEM (HLSTAGES * HLSTAGE_B)   // 147456 B

__device__ __forceinline__ void hl_issue(
    uint32_t stage, const __nv_bfloat16* Ah, const __nv_bfloat16* Al,
    const __nv_bfloat16* Wh, const __nv_bfloat16* Wl, int k0, int tid)
{
    const __nv_bfloat16* srcs[4] = { Ah, Al, Wh, Wl };
#pragma unroll
    for (int t = 0; t < 4; t++) {
        const uint32_t db = stage + t * HLTILE_B;
        const __nv_bfloat16* sb = srcs[t] + k0;
#pragma unroll
        for (int j = 0; j < 4; j++) {
            const int idx = tid + j * 256;
            const int row = idx >> 3;
            const int c   = idx & 7;
            CPA16(db + row * 144 + c * 16, sb + (size_t)row * H_ + c * 8);
        }
    }
}

__device__ __forceinline__ void gemm_hl_body(
    const __nv_bfloat16* __restrict__ Ah, const __nv_bfloat16* __restrict__ Al,
    const __nv_bfloat16* __restrict__ Wh, const __nv_bfloat16* __restrict__ Wl,
    const float* __restrict__ bias, float* __restrict__ C,
    char* gsm, int bm0, int bn0)
{
    const int tid  = threadIdx.x;
    const int wid  = tid >> 5;
    const int lane = tid & 31;
    const int wm   = wid & 1;
    const int wn   = wid >> 1;

    const uint32_t ubase = smem_u32(gsm);
    const uint32_t aLOff = (uint32_t)((wm * 64 + (lane & 15)) * 144 + (lane >> 4) * 16);
    const uint32_t bLOff = (uint32_t)((wn * 32 + ((lane >> 4) & 1) * 8 + (lane & 7)) * 144
                                      + ((lane >> 3) & 1) * 16);

    const __nv_bfloat16* At_h = Ah + (size_t)bm0 * H_;
    const __nv_bfloat16* At_l = Al + (size_t)bm0 * H_;
    const __nv_bfloat16* Wt_h = Wh + (size_t)bn0 * H_;
    const __nv_bfloat16* Wt_l = Wl + (size_t)bn0 * H_;

    float acc[4][4][4];
#pragma unroll
    for (int mi = 0; mi < 4; mi++)
#pragma unroll
        for (int nj = 0; nj < 4; nj++)
#pragma unroll
            for (int e = 0; e < 4; e++) acc[mi][nj][e] = 0.f;

    // prologue: stage 0
    hl_issue(ubase, At_h, At_l, Wt_h, Wt_l, 0, tid);
    CP_COMMIT();

    for (int c = 0; c < 16; c++) {
        // issue stage c+1 before waiting on stage c
        if (c < 15) {
            hl_issue(ubase + (uint32_t)((c + 1) & 1) * HLSTAGE_B,
                     At_h, At_l, Wt_h, Wt_l, (c + 1) * 64, tid);
            CP_COMMIT();
            CP_WAIT(1);
        } else {
            CP_WAIT(0);
        }
        __syncthreads();

        const uint32_t ub  = ubase + (uint32_t)(c & 1) * HLSTAGE_B;
        const uint32_t bAh = ub;
        const uint32_t bAl = ub + HLTILE_B;
        const uint32_t bWh = ub + 2 * HLTILE_B;
        const uint32_t bWl = ub + 3 * HLTILE_B;

#pragma unroll
        for (int ks = 0; ks < 4; ks++) {
            const uint32_t kb = (uint32_t)(ks * 32);
            uint32_t ah[4][4], al[4][4];
#pragma unroll
            for (int mi = 0; mi < 4; mi++) {
                const uint32_t rowb = (uint32_t)(mi * 16 * 144) + aLOff + kb;
                LDMX4(ah[mi][0], ah[mi][1], ah[mi][2], ah[mi][3], bAh + rowb);
                LDMX4(al[mi][0], al[mi][1], al[mi][2], al[mi][3], bAl + rowb);
            }
            uint32_t bh[4][2], bl[4][2];
#pragma unroll
            for (int pr = 0; pr < 2; pr++) {
                const uint32_t rowb = (uint32_t)(pr * 16 * 144) + bLOff + kb;
                LDMX4(bh[pr * 2][0], bh[pr * 2][1], bh[pr * 2 + 1][0], bh[pr * 2 + 1][1], bWh + rowb);
                LDMX4(bl[pr * 2][0], bl[pr * 2][1], bl[pr * 2 + 1][0], bl[pr * 2 + 1][1], bWl + rowb);
            }
#pragma unroll
            for (int mi = 0; mi < 4; mi++)
#pragma unroll
                for (int nj = 0; nj < 4; nj++) {
                    MMA16816(acc[mi][nj], ah[mi], bh[nj]);
                    MMA16816(acc[mi][nj], al[mi], bh[nj]);
                    MMA16816(acc[mi][nj], ah[mi], bl[nj]);
                }
        }
        __syncthreads();
    }

#pragma unroll
    for (int mi = 0; mi < 4; mi++) {
        const int r0 = bm0 + wm * 64 + mi * 16 + (lane >> 2);
#pragma unroll
        for (int nj = 0; nj < 4; nj++) {
            const int col = bn0 + wn * 32 + nj * 8 + (lane & 3) * 2;
            const float b0 = bias[col], b1 = bias[col + 1];
            float2 o0 = make_float2(acc[mi][nj][0] + b0, acc[mi][nj][1] + b1);
            float2 o1 = make_float2(acc[mi][nj][2] + b0, acc[mi][nj][3] + b1);
            *(float2*)(C + (size_t)r0 * H_ + col)       = o0;
            *(float2*)(C + (size_t)(r0 + 8) * H_ + col) = o1;
        }
    }
}

// Fused Q/K/V projections (z selects operand set), pre-converted operands.
__global__ __launch_bounds__(256, 1)
void qkv_hl(const float* __restrict__ bq, const float* __restrict__ bk,
            const float* __restrict__ bv,
            float* __restrict__ Qo, float* __restrict__ Ko, float* __restrict__ Vo)
{
    extern __shared__ char gsm[];
    const __nv_bfloat16 *Ah, *Al, *Wh, *Wl;
    const float* bias;
    float* C;
    if (blockIdx.z == 0)      { Ah = g_qh; Al = g_ql; Wh = g_wqh; Wl = g_wql; bias = bq; C = Qo; }
    else if (blockIdx.z == 1) { Ah = g_kh; Al = g_kl; Wh = g_wkh; Wl = g_wkl; bias = bk; C = Ko; }
    else                      { Ah = g_vh; Al = g_vl; Wh = g_wvh; Wl = g_wvl; bias = bv; C = Vo; }
    gemm_hl_body(Ah, Al, Wh, Wl, bias, C, gsm, blockIdx.y * 128, blockIdx.x * 128);
}

__global__ __launch_bounds__(256, 1)
void gemm_o_hl(const float* __restrict__ bias, float* __restrict__ C)
{
    extern __shared__ char gsm[];
    gemm_hl_body(g_ah, g_al, g_woh, g_wol, bias, C, gsm,
                 blockIdx.y * 128, blockIdx.x * 128);
}

// ===========================================================================
// Tensor-core flash attention (R7-exact, known-good).
// ===========================================================================
#define AT_ROW 72
#define AT_OP_ELEMS (64 * AT_ROW)
#define AT_STAGE_ELEMS (4 * AT_OP_ELEMS)
#define AT_STAGE_BYTES (AT_STAGE_ELEMS * 2)
#define ATTN_SMEM (2 * AT_STAGE_BYTES)

__device__ __forceinline__ void attn_load_kv(
    const float* Kp, const float* Vp, int tid, float4* kn, float4* vn)
{
#pragma unroll
    for (int i = 0; i < 4; i++) {
        const int slot = tid + i * 256;
        const int r  = slot >> 4;
        const int c4 = slot & 15;
        kn[i] = *(const float4*)(Kp + (size_t)r * H_ + c4 * 4);
        vn[i] = *(const float4*)(Vp + (size_t)r * H_ + c4 * 4);
    }
}

__device__ __forceinline__ void attn_stage_kv(
    __nv_bfloat16* st, int tid, const float4* kn, const float4* vn)
{
#pragma unroll
    for (int i = 0; i < 4; i++) {
        const int slot = tid + i * 256;
        const int r  = slot >> 4;
        const int c4 = slot & 15;
        const int off = r * AT_ROW + c4 * 4;
        float4 kv = kn[i];
        uint32_t kh01 = pack_hi(kv.x, kv.y), kh23 = pack_hi(kv.z, kv.w);
        *(uint32_t*)(st + off)     = kh01;
        *(uint32_t*)(st + off + 2) = kh23;
        *(uint32_t*)(st + AT_OP_ELEMS + off)     = pack_lo(kv.x, kv.y, kh01);
        *(uint32_t*)(st + AT_OP_ELEMS + off + 2) = pack_lo(kv.z, kv.w, kh23);
        float4 vv = vn[i];
        uint32_t vh01 = pack_hi(vv.x, vv.y), vh23 = pack_hi(vv.z, vv.w);
        *(uint32_t*)(st + 2 * AT_OP_ELEMS + off)     = vh01;
        *(uint32_t*)(st + 2 * AT_OP_ELEMS + off + 2) = vh23;
        *(uint32_t*)(st + 3 * AT_OP_ELEMS + off)     = pack_lo(vv.x, vv.y, vh01);
        *(uint32_t*)(st + 3 * AT_OP_ELEMS + off + 2) = pack_lo(vv.z, vv.w, vh23);
    }
}

__global__ __launch_bounds__(256, 1)
void attn_tc(const float* __restrict__ Qm, const float* __restrict__ Km,
             const float* __restrict__ Vm, const int* __restrict__ mask,
             float* __restrict__ O)
{
    extern __shared__ __nv_bfloat16 asmem[];
    __shared__ uint32_t mbits[2][2];

    const int tid  = threadIdx.x;
    const int wid  = tid >> 5;
    const int lane = tid & 31;
    const int qt = blockIdx.x;
    const int h  = blockIdx.y;
    const int b  = blockIdx.z;

    const uint32_t ubase = smem_u32(asmem);

    const int r0 = wid * 16 + (lane >> 2);
    const float* Qb = Qm + ((size_t)(b * S_ + qt * 128)) * H_ + h * HD_;
    uint32_t qh[4][4], ql[4][4];
#pragma unroll
    for (int ks = 0; ks < 4; ks++) {
        const int kb = ks * 16 + (lane & 3) * 2;
        float2 v0 = *(const float2*)(Qb + (size_t)r0 * H_ + kb);
        float2 v1 = *(const float2*)(Qb + (size_t)(r0 + 8) * H_ + kb);
        float2 v2 = *(const float2*)(Qb + (size_t)r0 * H_ + kb + 8);
        float2 v3 = *(const float2*)(Qb + (size_t)(r0 + 8) * H_ + kb + 8);
        qh[ks][0] = pack_hi(v0.x, v0.y);  ql[ks][0] = pack_lo(v0.x, v0.y, qh[ks][0]);
        qh[ks][1] = pack_hi(v1.x, v1.y);  ql[ks][1] = pack_lo(v1.x, v1.y, qh[ks][1]);
        qh[ks][2] = pack_hi(v2.x, v2.y);  ql[ks][2] = pack_lo(v2.x, v2.y, qh[ks][2]);
        qh[ks][3] = pack_hi(v3.x, v3.y);  ql[ks][3] = pack_lo(v3.x, v3.y, qh[ks][3]);
    }

    float oacc[8][4];
#pragma unroll
    for (int nj = 0; nj < 8; nj++)
#pragma unroll
        for (int e = 0; e < 4; e++) oacc[nj][e] = 0.f;
    float m0 = -1e30f, m1 = -1e30f, l0 = 0.f, l1 = 0.f;

    const float* Kb = Km + ((size_t)b * S_) * H_ + h * HD_;
    const float* Vb = Vm + ((size_t)b * S_) * H_ + h * HD_;

    float4 kn[4], vn[4];
    attn_load_kv(Kb, Vb, tid, kn, vn);
    attn_stage_kv(asmem, tid, kn, vn);
    int mv0 = 0, mv1 = 0;
    if (wid == 0) {
        mv0 = mask[(size_t)b * S_ + lane];
        mv1 = mask[(size_t)b * S_ + 32 + lane];
        unsigned b0v = __ballot_sync(0xffffffffu, mv0 != 0);
        unsigned b1v = __ballot_sync(0xffffffffu, mv1 != 0);
        if (lane == 0) { mbits[0][0] = b0v; mbits[0][1] = b1v; }
    }

    for (int kt = 0; kt < 16; kt++) {
        const int sel = kt & 1;
        __syncthreads();
        const uint32_t mw0 = mbits[sel][0];
        const uint32_t mw1 = mbits[sel][1];
        const uint32_t ub  = ubase + (uint32_t)sel * AT_STAGE_BYTES;
        const uint32_t bKh = ub;
        const uint32_t bKl = ub + AT_OP_ELEMS * 2;
        const uint32_t bVh = ub + 2 * AT_OP_ELEMS * 2;
        const uint32_t bVl = ub + 3 * AT_OP_ELEMS * 2;

        float sacc[8][4];
#pragma unroll
        for (int nj = 0; nj < 8; nj++)
#pragma unroll
            for (int e = 0; e < 4; e++) sacc[nj][e] = 0.f;

#pragma unroll
        for (int ks = 0; ks < 4; ks++) {
            uint32_t bh[8][2], bl[8][2];
#pragma unroll
            for (int g = 0; g < 4; g++) {
                const uint32_t rowb =
                    (uint32_t)((g * 16 + ((lane >> 4) & 1) * 8 + (lane & 7)) * (AT_ROW * 2)
                               + ks * 32 + ((lane >> 3) & 1) * 16);
                LDMX4(bh[2 * g][0], bh[2 * g][1], bh[2 * g + 1][0], bh[2 * g + 1][1], bKh + rowb);
                LDMX4(bl[2 * g][0], bl[2 * g][1], bl[2 * g + 1][0], bl[2 * g + 1][1], bKl + rowb);
            }
#pragma unroll
            for (int nj = 0; nj < 8; nj++) {
                MMA16816(sacc[nj], qh[ks], bh[nj]);
                MMA16816(sacc[nj], ql[ks], bh[nj]);
                MMA16816(sacc[nj], qh[ks], bl[nj]);
            }
        }

        if (kt < 15) {
            attn_load_kv(Kb + (size_t)(kt + 1) * 64 * H_,
                         Vb + (size_t)(kt + 1) * 64 * H_, tid, kn, vn);
            if (wid == 0) {
                mv0 = mask[(size_t)b * S_ + (kt + 1) * 64 + lane];
                mv1 = mask[(size_t)b * S_ + (kt + 1) * 64 + 32 + lane];
            }
        }

        const int shb = (lane & 3) * 2;
        float mx0 = -1e30f, mx1 = -1e30f;
#pragma unroll
        for (int nj = 0; nj < 8; nj++) {
            const uint32_t w = (nj < 4) ? mw0 : mw1;
            const int sh = (nj & 3) * 8 + shb;
            const bool k0 = (w >> sh) & 1;
            const bool k1 = (w >> (sh + 1)) & 1;
            float s0 = k0 ? -1e30f : sacc[nj][0] * 0.03125f;
            float s1 = k1 ? -1e30f : sacc[nj][1] * 0.03125f;
            float s2 = k0 ? -1e30f : sacc[nj][2] * 0.03125f;
            float s3 = k1 ? -1e30f : sacc[nj][3] * 0.03125f;
            sacc[nj][0] = s0; sacc[nj][1] = s1; sacc[nj][2] = s2; sacc[nj][3] = s3;
            mx0 = fmaxf(mx0, fmaxf(s0, s1));
            mx1 = fmaxf(mx1, fmaxf(s2, s3));
        }
        mx0 = fmaxf(mx0, __shfl_xor_sync(0xffffffffu, mx0, 1));
        mx0 = fmaxf(mx0, __shfl_xor_sync(0xffffffffu, mx0, 2));
        mx1 = fmaxf(mx1, __shfl_xor_sync(0xffffffffu, mx1, 1));
        mx1 = fmaxf(mx1, __shfl_xor_sync(0xffffffffu, mx1, 2));

        const float nm0 = fmaxf(m0, mx0);
        const float nm1 = fmaxf(m1, mx1);
        const float f0 = __expf(m0 - nm0);
        const float f1 = __expf(m1 - nm1);
        m0 = nm0; m1 = nm1;
        l0 *= f0;  l1 *= f1;
#pragma unroll
        for (int nj = 0; nj < 8; nj++) {
            oacc[nj][0] *= f0; oacc[nj][1] *= f0;
            oacc[nj][2] *= f1; oacc[nj][3] *= f1;
        }

        uint32_t pHa[8], pHb[8], pLa[8], pLb[8];
        float ps0 = 0.f, ps1 = 0.f;
#pragma unroll
        for (int nj = 0; nj < 8; nj++) {
            float p0 = __expf(sacc[nj][0] - nm0);
            float p1 = __expf(sacc[nj][1] - nm0);
            float p2 = __expf(sacc[nj][2] - nm1);
            float p3 = __expf(sacc[nj][3] - nm1);
            ps0 += p0 + p1;
            ps1 += p2 + p3;
            pHa[nj] = pack_hi(p0, p1);  pLa[nj] = pack_lo(p0, p1, pHa[nj]);
            pHb[nj] = pack_hi(p2, p3);  pLb[nj] = pack_lo(p2, p3, pHb[nj]);
        }
        l0 += ps0;
        l1 += ps1;

#pragma unroll
        for (int kk = 0; kk < 4; kk++) {
            uint32_t aH[4] = { pHa[2 * kk], pHb[2 * kk], pHa[2 * kk + 1], pHb[2 * kk + 1] };
            uint32_t aL[4] = { pLa[2 * kk], pLb[2 * kk], pLa[2 * kk + 1], pLb[2 * kk + 1] };
#pragma unroll
            for (int njp = 0; njp < 8; njp += 2) {
                const uint32_t rowb =
                    (uint32_t)((kk * 16 + (lane & 15)) * (AT_ROW * 2)
                               + (njp + ((lane >> 4) & 1)) * 16);
                uint32_t vh[2][2], vl[2][2];
                LDMX4T(vh[0][0], vh[0][1], vh[1][0], vh[1][1], bVh + rowb);
                LDMX4T(vl[0][0], vl[0][1], vl[1][0], vl[1][1], bVl + rowb);
                MMA16816(oacc[njp],     aH, vh[0]);
                MMA16816(oacc[njp],     aL, vh[0]);
                MMA16816(oacc[njp],     aH, vl[0]);
                MMA16816(oacc[njp + 1], aH, vh[1]);
                MMA16816(oacc[njp + 1], aL, vh[1]);
                MMA16816(oacc[njp + 1], aH, vl[1]);
            }
        }

        if (kt < 15) {
            attn_stage_kv(asmem + (sel ^ 1) * AT_STAGE_ELEMS, tid, kn, vn);
            if (wid == 0) {
                unsigned b0v = __ballot_sync(0xffffffffu, mv0 != 0);
                unsigned b1v = __ballot_sync(0xffffffffu, mv1 != 0);
                if (lane == 0) { mbits[sel ^ 1][0] = b0v; mbits[sel ^ 1][1] = b1v; }
            }
        }
    }

    l0 += __shfl_xor_sync(0xffffffffu, l0, 1);
    l0 += __shfl_xor_sync(0xffffffffu, l0, 2);
    l1 += __shfl_xor_sync(0xffffffffu, l1, 1);
    l1 += __shfl_xor_sync(0xffffffffu, l1, 2);
    const float rl0 = 1.f / l0;
    const float rl1 = 1.f / l1;

    float* Ob = O + ((size_t)(b * S_ + qt * 128)) * H_ + h * HD_;
#pragma unroll
    for (int nj = 0; nj < 8; nj++) {
        const int colb = nj * 8 + (lane & 3) * 2;
        *(float2*)(Ob + (size_t)r0 * H_ + colb) =
            make_float2(oacc[nj][0] * rl0, oacc[nj][1] * rl0);
        *(float2*)(Ob + (size_t)(r0 + 8) * H_ + colb) =
            make_float2(oacc[nj][2] * rl1, oacc[nj][3] * rl1);
    }
}

// ---------------------------------------------------------------------------
extern "C" void kernel_launch(void* const* d_in, const int* in_sizes, int n_in,
                              void* d_out, int out_size)
{
    const float* query = (const float*)d_in[0];
    const float* key   = (const float*)d_in[1];
    const float* value = (const float*)d_in[2];
    const int*   mask  = (const int*)d_in[3];

    const int wb = (n_in >= 13) ? 5 : 4;
    const float* Wq = (const float*)d_in[wb + 0];
    const float* bq = (const float*)d_in[wb + 1];
    const float* Wk = (const float*)d_in[wb + 2];
    const float* bk = (const float*)d_in[wb + 3];
    const float* Wv = (const float*)d_in[wb + 4];
    const float* bv = (const float*)d_in[wb + 5];
    const float* Wo = (const float*)d_in[wb + 6];
    const float* bo = (const float*)d_in[wb + 7];
    float* out = (float*)d_out;

    float *dQ, *dK, *dV, *dA;
    cudaGetSymbolAddress((void**)&dQ, g_Q);
    cudaGetSymbolAddress((void**)&dK, g_K);
    cudaGetSymbolAddress((void**)&dV, g_V);
    cudaGetSymbolAddress((void**)&dA, g_A);
    __nv_bfloat16 *qh, *ql, *kh, *kl, *vh, *vl, *ah, *al;
    __nv_bfloat16 *wqh, *wql, *wkh, *wkl, *wvh, *wvl, *woh, *wol;
    cudaGetSymbolAddress((void**)&qh, g_qh);  cudaGetSymbolAddress((void**)&ql, g_ql);
    cudaGetSymbolAddress((void**)&kh, g_kh);  cudaGetSymbolAddress((void**)&kl, g_kl);
    cudaGetSymbolAddress((void**)&vh, g_vh);  cudaGetSymbolAddress((void**)&vl, g_vl);
    cudaGetSymbolAddress((void**)&ah, g_ah);  cudaGetSymbolAddress((void**)&al, g_al);
    cudaGetSymbolAddress((void**)&wqh, g_wqh); cudaGetSymbolAddress((void**)&wql, g_wql);
    cudaGetSymbolAddress((void**)&wkh, g_wkh); cudaGetSymbolAddress((void**)&wkl, g_wkl);
    cudaGetSymbolAddress((void**)&wvh, g_wvh); cudaGetSymbolAddress((void**)&wvl, g_wvl);
    cudaGetSymbolAddress((void**)&woh, g_woh); cudaGetSymbolAddress((void**)&wol, g_wol);

    cudaFuncSetAttribute(qkv_hl,    cudaFuncAttributeMaxDynamicSharedMemorySize, GEMM_SMEM);
    cudaFuncSetAttribute(gemm_o_hl, cudaFuncAttributeMaxDynamicSharedMemorySize, GEMM_SMEM);
    cudaFuncSetAttribute(attn_tc,   cudaFuncAttributeMaxDynamicSharedMemorySize, ATTN_SMEM);

    const int nBig = MROWS * H_ / 4;   // 2M float4
    const int nWt  = H_ * H_ / 4;      // 256K float4
    conv_hl<<<2048, 256>>>(query, qh, ql, nBig);
    conv_hl<<<2048, 256>>>(key,   kh, kl, nBig);
    conv_hl<<<2048, 256>>>(value, vh, vl, nBig);
    conv_hl<<<512, 256>>>(Wq, wqh, wql, nWt);
    conv_hl<<<512, 256>>>(Wk, wkh, wkl, nWt);
    conv_hl<<<512, 256>>>(Wv, wvh, wvl, nWt);
    conv_hl<<<512, 256>>>(Wo, woh, wol, nWt);

    dim3 qkvgrid(H_ / 128, MROWS / 128, 3);  // (8, 64, 3)
    qkv_hl<<<qkvgrid, 256, GEMM_SMEM>>>(bq, bk, bv, dQ, dK, dV);

    dim3 agrid(S_ / 128, NH_, B_);           // (8, 16, 8)
    attn_tc<<<agrid, 256, ATTN_SMEM>>>(dQ, dK, dV, mask, dA);

    conv_hl<<<2048, 256>>>(dA, ah, al, nBig);

    dim3 ggrid(H_ / 128, MROWS / 128);       // (8, 64)
    gemm_o_hl<<<ggrid, 256, GEMM_SMEM>>>(bo, out);
}

// round 11
// speedup vs baseline: 1.0847x; 1.0006x over previous
#include <cuda_runtime.h>
#include <cuda_bf16.h>
#include <cstdint>

#define B_  8
#define S_  1024
#define H_  1024
#define NH_ 16
#define HD_ 64
#define MROWS (B_ * S_)
#define NBIG (MROWS * H_)

// Pre-converted input activations (hi/lo bf16)
__device__ __nv_bfloat16 g_xqh[NBIG], g_xql[NBIG];
__device__ __nv_bfloat16 g_xkh[NBIG], g_xkl[NBIG];
__device__ __nv_bfloat16 g_xvh[NBIG], g_xvl[NBIG];
// Projections (written split by qkv GEMM, consumed by attention)
__device__ __nv_bfloat16 g_qh[NBIG], g_ql[NBIG];
__device__ __nv_bfloat16 g_kh[NBIG], g_kl[NBIG];
__device__ __nv_bfloat16 g_vh[NBIG], g_vl[NBIG];
// Attention output (written split by attention, consumed by O GEMM)
__device__ __nv_bfloat16 g_ah[NBIG], g_al[NBIG];
// Weights (hi/lo)
__device__ __nv_bfloat16 g_wqh[H_ * H_], g_wql[H_ * H_];
__device__ __nv_bfloat16 g_wkh[H_ * H_], g_wkl[H_ * H_];
__device__ __nv_bfloat16 g_wvh[H_ * H_], g_wvl[H_ * H_];
__device__ __nv_bfloat16 g_woh[H_ * H_], g_wol[H_ * H_];

__device__ __forceinline__ uint32_t smem_u32(const void* p) {
    uint32_t a;
    asm("{ .reg .u64 t; cvta.to.shared.u64 t, %1; cvt.u32.u64 %0, t; }"
        : "=r"(a) : "l"(p));
    return a;
}

#define LDMX4(r0, r1, r2, r3, addr) \
    asm volatile("ldmatrix.sync.aligned.m8n8.x4.shared.b16 {%0,%1,%2,%3}, [%4];" \
                 : "=r"(r0), "=r"(r1), "=r"(r2), "=r"(r3) : "r"(addr))

#define LDMX4T(r0, r1, r2, r3, addr) \
    asm volatile("ldmatrix.sync.aligned.m8n8.x4.trans.shared.b16 {%0,%1,%2,%3}, [%4];" \
                 : "=r"(r0), "=r"(r1), "=r"(r2), "=r"(r3) : "r"(addr))

#define MMA16816(d, a, b) \
    asm volatile("mma.sync.aligned.m16n8k16.row.col.f32.bf16.bf16.f32 " \
                 "{%0,%1,%2,%3}, {%4,%5,%6,%7}, {%8,%9}, {%0,%1,%2,%3};" \
                 : "+f"((d)[0]), "+f"((d)[1]), "+f"((d)[2]), "+f"((d)[3]) \
                 : "r"((a)[0]), "r"((a)[1]), "r"((a)[2]), "r"((a)[3]), \
                   "r"((b)[0]), "r"((b)[1]))

#define CPA16(dst, src) \
    asm volatile("cp.async.cg.shared.global [%0], [%1], 16;" :: "r"(dst), "l"(src))
#define CP_COMMIT() asm volatile("cp.async.commit_group;")
#define CP_WAIT(n)  asm volatile("cp.async.wait_group %0;" :: "n"(n))

__device__ __forceinline__ uint32_t pack_hi(float x, float y) {
    __nv_bfloat162 h = __float22bfloat162_rn(make_float2(x, y));
    return *(uint32_t*)&h;
}
__device__ __forceinline__ uint32_t pack_lo(float x, float y, uint32_t hi) {
    __nv_bfloat162 h = *(__nv_bfloat162*)&hi;
    __nv_bfloat162 l = __float22bfloat162_rn(make_float2(
        x - __bfloat162float(h.x), y - __bfloat162float(h.y)));
    return *(uint32_t*)&l;
}

// ===========================================================================
// fp32 -> bf16 hi/lo split convert. Each thread: 2 float4 in, 1 uint4 per
// output array (vectorized stores).
// ===========================================================================
__global__ __launch_bounds__(256)
void conv_hl(const float* __restrict__ src, __nv_bfloat16* __restrict__ hi,
             __nv_bfloat16* __restrict__ lo, int n8)
{
    for (int i = blockIdx.x * blockDim.x + threadIdx.x; i < n8;
         i += gridDim.x * blockDim.x) {
        float4 a = ((const float4*)src)[2 * i];
        float4 b = ((const float4*)src)[2 * i + 1];
        uint32_t h0 = pack_hi(a.x, a.y), h1 = pack_hi(a.z, a.w);
        uint32_t h2 = pack_hi(b.x, b.y), h3 = pack_hi(b.z, b.w);
        uint32_t l0 = pack_lo(a.x, a.y, h0), l1 = pack_lo(a.z, a.w, h1);
        uint32_t l2 = pack_lo(b.x, b.y, h2), l3 = pack_lo(b.z, b.w, h3);
        ((uint4*)hi)[i] = make_uint4(h0, h1, h2, h3);
        ((uint4*)lo)[i] = make_uint4(l0, l1, l2, l3);
    }
}

// ===========================================================================
// Pre-converted bf16 hi/lo GEMM (R10 structure, passing). 128x128 tile,
// BK=64, 2-stage cp.async pipeline. Epilogue either fp32 or split bf16.
// ===========================================================================
#define HLTILE_B  (128 * 72 * 2)        // 18432 B per operand tile
#define HLSTAGE_B (4 * HLTILE_B)        // 73728 B
#define GEMM_SMEM (2 * HLSTAGE_B)       // 147456 B

__device__ __forceinline__ void hl_issue(
    uint32_t stage, const __nv_bfloat16* Ah, const __nv_bfloat16* Al,
    const __nv_bfloat16* Wh, const __nv_bfloat16* Wl, int k0, int tid)
{
    const __nv_bfloat16* srcs[4] = { Ah, Al, Wh, Wl };
#pragma unroll
    for (int t = 0; t < 4; t++) {
        const uint32_t db = stage + t * HLTILE_B;
        const __nv_bfloat16* sb = srcs[t] + k0;
#pragma unroll
        for (int j = 0; j < 4; j++) {
            const int idx = tid + j * 256;
            const int row = idx >> 3;
            const int c   = idx & 7;
            CPA16(db + row * 144 + c * 16, sb + (size_t)row * H_ + c * 8);
        }
    }
}

template<int SPLIT>
__device__ __forceinline__ void gemm_hl_body(
    const __nv_bfloat16* __restrict__ Ah, const __nv_bfloat16* __restrict__ Al,
    const __nv_bfloat16* __restrict__ Wh, const __nv_bfloat16* __restrict__ Wl,
    const float* __restrict__ bias, float* __restrict__ C,
    __nv_bfloat16* __restrict__ Ch, __nv_bfloat16* __restrict__ Cl,
    char* gsm, int bm0, int bn0)
{
    const int tid  = threadIdx.x;
    const int wid  = tid >> 5;
    const int lane = tid & 31;
    const int wm   = wid & 1;
    const int wn   = wid >> 1;

    const uint32_t ubase = smem_u32(gsm);
    const uint32_t aLOff = (uint32_t)((wm * 64 + (lane & 15)) * 144 + (lane >> 4) * 16);
    const uint32_t bLOff = (uint32_t)((wn * 32 + ((lane >> 4) & 1) * 8 + (lane & 7)) * 144
                                      + ((lane >> 3) & 1) * 16);

    const __nv_bfloat16* At_h = Ah + (size_t)bm0 * H_;
    const __nv_bfloat16* At_l = Al + (size_t)bm0 * H_;
    const __nv_bfloat16* Wt_h = Wh + (size_t)bn0 * H_;
    const __nv_bfloat16* Wt_l = Wl + (size_t)bn0 * H_;

    float acc[4][4][4];
#pragma unroll
    for (int mi = 0; mi < 4; mi++)
#pragma unroll
        for (int nj = 0; nj < 4; nj++)
#pragma unroll
            for (int e = 0; e < 4; e++) acc[mi][nj][e] = 0.f;

    hl_issue(ubase, At_h, At_l, Wt_h, Wt_l, 0, tid);
    CP_COMMIT();

    for (int c = 0; c < 16; c++) {
        if (c < 15) {
            hl_issue(ubase + (uint32_t)((c + 1) & 1) * HLSTAGE_B,
                     At_h, At_l, Wt_h, Wt_l, (c + 1) * 64, tid);
            CP_COMMIT();
            CP_WAIT(1);
        } else {
            CP_WAIT(0);
        }
        __syncthreads();

        const uint32_t ub  = ubase + (uint32_t)(c & 1) * HLSTAGE_B;
        const uint32_t bAh = ub;
        const uint32_t bAl = ub + HLTILE_B;
        const uint32_t bWh = ub + 2 * HLTILE_B;
        const uint32_t bWl = ub + 3 * HLTILE_B;

#pragma unroll
        for (int ks = 0; ks < 4; ks++) {
            const uint32_t kb = (uint32_t)(ks * 32);
            uint32_t ah[4][4], al[4][4];
#pragma unroll
            for (int mi = 0; mi < 4; mi++) {
                const uint32_t rowb = (uint32_t)(mi * 16 * 144) + aLOff + kb;
                LDMX4(ah[mi][0], ah[mi][1], ah[mi][2], ah[mi][3], bAh + rowb);
                LDMX4(al[mi][0], al[mi][1], al[mi][2], al[mi][3], bAl + rowb);
            }
            uint32_t bh[4][2], bl[4][2];
#pragma unroll
            for (int pr = 0; pr < 2; pr++) {
                const uint32_t rowb = (uint32_t)(pr * 16 * 144) + bLOff + kb;
                LDMX4(bh[pr * 2][0], bh[pr * 2][1], bh[pr * 2 + 1][0], bh[pr * 2 + 1][1], bWh + rowb);
                LDMX4(bl[pr * 2][0], bl[pr * 2][1], bl[pr * 2 + 1][0], bl[pr * 2 + 1][1], bWl + rowb);
            }
#pragma unroll
            for (int mi = 0; mi < 4; mi++)
#pragma unroll
                for (int nj = 0; nj < 4; nj++) {
                    MMA16816(acc[mi][nj], ah[mi], bh[nj]);
                    MMA16816(acc[mi][nj], al[mi], bh[nj]);
                    MMA16816(acc[mi][nj], ah[mi], bl[nj]);
                }
        }
        __syncthreads();
    }

#pragma unroll
    for (int mi = 0; mi < 4; mi++) {
        const int r0 = bm0 + wm * 64 + mi * 16 + (lane >> 2);
#pragma unroll
        for (int nj = 0; nj < 4; nj++) {
            const int col = bn0 + wn * 32 + nj * 8 + (lane & 3) * 2;
            const float b0 = bias[col], b1 = bias[col + 1];
            float o0x = acc[mi][nj][0] + b0, o0y = acc[mi][nj][1] + b1;
            float o1x = acc[mi][nj][2] + b0, o1y = acc[mi][nj][3] + b1;
            if (SPLIT) {
                uint32_t h0 = pack_hi(o0x, o0y);
                uint32_t h1 = pack_hi(o1x, o1y);
                *(uint32_t*)(Ch + (size_t)r0 * H_ + col)       = h0;
                *(uint32_t*)(Ch + (size_t)(r0 + 8) * H_ + col) = h1;
                *(uint32_t*)(Cl + (size_t)r0 * H_ + col)       = pack_lo(o0x, o0y, h0);
                *(uint32_t*)(Cl + (size_t)(r0 + 8) * H_ + col) = pack_lo(o1x, o1y, h1);
            } else {
                *(float2*)(C + (size_t)r0 * H_ + col)       = make_float2(o0x, o0y);
                *(float2*)(C + (size_t)(r0 + 8) * H_ + col) = make_float2(o1x, o1y);
            }
        }
    }
}

// Fused Q/K/V projections: split bf16 outputs.
__global__ __launch_bounds__(256, 1)
void qkv_hl(const float* __restrict__ bq, const float* __restrict__ bk,
            const float* __restrict__ bv)
{
    extern __shared__ char gsm[];
    const __nv_bfloat16 *Ah, *Al, *Wh, *Wl;
    const float* bias;
    __nv_bfloat16 *Ch, *Cl;
    if (blockIdx.z == 0)      { Ah = g_xqh; Al = g_xql; Wh = g_wqh; Wl = g_wql; bias = bq; Ch = g_qh; Cl = g_ql; }
    else if (blockIdx.z == 1) { Ah = g_xkh; Al = g_xkl; Wh = g_wkh; Wl = g_wkl; bias = bk; Ch = g_kh; Cl = g_kl; }
    else                      { Ah = g_xvh; Al = g_xvl; Wh = g_wvh; Wl = g_wvl; bias = bv; Ch = g_vh; Cl = g_vl; }
    gemm_hl_body<1>(Ah, Al, Wh, Wl, bias, nullptr, Ch, Cl, gsm,
                    blockIdx.y * 128, blockIdx.x * 128);
}

__global__ __launch_bounds__(256, 1)
void gemm_o_hl(const float* __restrict__ bias, float* __restrict__ C)
{
    extern __shared__ char gsm[];
    gemm_hl_body<0>(g_ah, g_al, g_woh, g_wol, bias, C, nullptr, nullptr, gsm,
                    blockIdx.y * 128, blockIdx.x * 128);
}

// ===========================================================================
// Tensor-core flash attention on pre-split K/V: staging is pure cp.async,
// no conversion ALU. BQ=128 (8 warps), double-buffered; mask ballots hoisted.
// Writes output pre-split (g_ah/g_al). Scale 1/32.
// ===========================================================================
#define AT_TILE_B  (64 * 144)           // 9216 B per operand tile
#define AT_STAGE_B (4 * AT_TILE_B)      // 36864
#define ATTN_SMEM  (2 * AT_STAGE_B)     // 73728

__device__ __forceinline__ void attn_issue(
    uint32_t stage, const __nv_bfloat16* Kh, const __nv_bfloat16* Kl,
    const __nv_bfloat16* Vh, const __nv_bfloat16* Vl, int tid)
{
    const __nv_bfloat16* srcs[4] = { Kh, Kl, Vh, Vl };
#pragma unroll
    for (int t = 0; t < 4; t++) {
        const uint32_t db = stage + t * AT_TILE_B;
        const __nv_bfloat16* sb = srcs[t];
#pragma unroll
        for (int j = 0; j < 2; j++) {
            const int idx = tid + j * 256;
            const int row = idx >> 3;
            const int c   = idx & 7;
            CPA16(db + row * 144 + c * 16, sb + (size_t)row * H_ + c * 8);
        }
    }
}

__global__ __launch_bounds__(256, 1)
void attn_tc(const int* __restrict__ mask)
{
    extern __shared__ char asmem[];
    __shared__ uint32_t s_mb[32];

    const int tid  = threadIdx.x;
    const int wid  = tid >> 5;
    const int lane = tid & 31;
    const int qt = blockIdx.x;
    const int h  = blockIdx.y;
    const int b  = blockIdx.z;

    const uint32_t ubase = smem_u32(asmem);

    // ---- Q fragments straight from pre-split arrays ----
    const int r0 = wid * 16 + (lane >> 2);
    const size_t qoff = ((size_t)(b * S_ + qt * 128)) * H_ + h * HD_;
    const __nv_bfloat16* Qhb = g_qh + qoff;
    const __nv_bfloat16* Qlb = g_ql + qoff;
    uint32_t qh[4][4], ql[4][4];
#pragma unroll
    for (int ks = 0; ks < 4; ks++) {
        const int kb = ks * 16 + (lane & 3) * 2;
        qh[ks][0] = *(const uint32_t*)(Qhb + (size_t)r0 * H_ + kb);
        qh[ks][1] = *(const uint32_t*)(Qhb + (size_t)(r0 + 8) * H_ + kb);
        qh[ks][2] = *(const uint32_t*)(Qhb + (size_t)r0 * H_ + kb + 8);
        qh[ks][3] = *(const uint32_t*)(Qhb + (size_t)(r0 + 8) * H_ + kb + 8);
        ql[ks][0] = *(const uint32_t*)(Qlb + (size_t)r0 * H_ + kb);
        ql[ks][1] = *(const uint32_t*)(Qlb + (size_t)(r0 + 8) * H_ + kb);
        ql[ks][2] = *(const uint32_t*)(Qlb + (size_t)r0 * H_ + kb + 8);
        ql[ks][3] = *(const uint32_t*)(Qlb + (size_t)(r0 + 8) * H_ + kb + 8);
    }

    // ---- all mask ballots up front: warp w computes words 4w..4w+3 ----
    {
        int mv[4];
#pragma unroll
        for (int j = 0; j < 4; j++)
            mv[j] = mask[(size_t)b * S_ + (wid * 4 + j) * 32 + lane];
#pragma unroll
        for (int j = 0; j < 4; j++) {
            unsigned bv = __ballot_sync(0xffffffffu, mv[j] != 0);
            if (lane == 0) s_mb[wid * 4 + j] = bv;
        }
    }

    float oacc[8][4];
#pragma unroll
    for (int nj = 0; nj < 8; nj++)
#pragma unroll
        for (int e = 0; e < 4; e++) oacc[nj][e] = 0.f;
    float m0 = -1e30f, m1 = -1e30f, l0 = 0.f, l1 = 0.f;

    const size_t koff = (size_t)b * S_ * H_ + h * HD_;
    const __nv_bfloat16* Khb = g_kh + koff;
    const __nv_bfloat16* Klb = g_kl + koff;
    const __nv_bfloat16* Vhb = g_vh + koff;
    const __nv_bfloat16* Vlb = g_vl + koff;

    attn_issue(ubase, Khb, Klb, Vhb, Vlb, tid);
    CP_COMMIT();

    for (int kt = 0; kt < 16; kt++) {
        const int sel = kt & 1;
        CP_WAIT(0);
        __syncthreads();
        if (kt < 15) {
            const size_t toff = (size_t)(kt + 1) * 64 * H_;
            attn_issue(ubase + (uint32_t)(sel ^ 1) * AT_STAGE_B,
                       Khb + toff, Klb + toff, Vhb + toff, Vlb + toff, tid);
            CP_COMMIT();
        }
        const uint32_t mw0 = s_mb[2 * kt];
        const uint32_t mw1 = s_mb[2 * kt + 1];
        const uint32_t ub  = ubase + (uint32_t)sel * AT_STAGE_B;
        const uint32_t bKh = ub;
        const uint32_t bKl = ub + AT_TILE_B;
        const uint32_t bVh = ub + 2 * AT_TILE_B;
        const uint32_t bVl = ub + 3 * AT_TILE_B;

        // ---- S = Q K^T ----
        float sacc[8][4];
#pragma unroll
        for (int nj = 0; nj < 8; nj++)
#pragma unroll
            for (int e = 0; e < 4; e++) sacc[nj][e] = 0.f;

#pragma unroll
        for (int ks = 0; ks < 4; ks++) {
            uint32_t bh[8][2], bl[8][2];
#pragma unroll
            for (int g = 0; g < 4; g++) {
                const uint32_t rowb =
                    (uint32_t)((g * 16 + ((lane >> 4) & 1) * 8 + (lane & 7)) * 144
                               + ks * 32 + ((lane >> 3) & 1) * 16);
                LDMX4(bh[2 * g][0], bh[2 * g][1], bh[2 * g + 1][0], bh[2 * g + 1][1], bKh + rowb);
                LDMX4(bl[2 * g][0], bl[2 * g][1], bl[2 * g + 1][0], bl[2 * g + 1][1], bKl + rowb);
            }
#pragma unroll
            for (int nj = 0; nj < 8; nj++) {
                MMA16816(sacc[nj], qh[ks], bh[nj]);
                MMA16816(sacc[nj], ql[ks], bh[nj]);
                MMA16816(sacc[nj], qh[ks], bl[nj]);
            }
        }

        // ---- per-tile softmax ----
        const int shb = (lane & 3) * 2;
        float mx0 = -1e30f, mx1 = -1e30f;
#pragma unroll
        for (int nj = 0; nj < 8; nj++) {
            const uint32_t w = (nj < 4) ? mw0 : mw1;
            const int sh = (nj & 3) * 8 + shb;
            const bool k0 = (w >> sh) & 1;
            const bool k1 = (w >> (sh + 1)) & 1;
            float s0 = k0 ? -1e30f : sacc[nj][0] * 0.03125f;
            float s1 = k1 ? -1e30f : sacc[nj][1] * 0.03125f;
            float s2 = k0 ? -1e30f : sacc[nj][2] * 0.03125f;
            float s3 = k1 ? -1e30f : sacc[nj][3] * 0.03125f;
            sacc[nj][0] = s0; sacc[nj][1] = s1; sacc[nj][2] = s2; sacc[nj][3] = s3;
            mx0 = fmaxf(mx0, fmaxf(s0, s1));
            mx1 = fmaxf(mx1, fmaxf(s2, s3));
        }
        mx0 = fmaxf(mx0, __shfl_xor_sync(0xffffffffu, mx0, 1));
        mx0 = fmaxf(mx0, __shfl_xor_sync(0xffffffffu, mx0, 2));
        mx1 = fmaxf(mx1, __shfl_xor_sync(0xffffffffu, mx1, 1));
        mx1 = fmaxf(mx1, __shfl_xor_sync(0xffffffffu, mx1, 2));

        const float nm0 = fmaxf(m0, mx0);
        const float nm1 = fmaxf(m1, mx1);
        const float f0 = __expf(m0 - nm0);
        const float f1 = __expf(m1 - nm1);
        m0 = nm0; m1 = nm1;
        l0 *= f0;  l1 *= f1;
#pragma unroll
        for (int nj = 0; nj < 8; nj++) {
            oacc[nj][0] *= f0; oacc[nj][1] *= f0;
            oacc[nj][2] *= f1; oacc[nj][3] *= f1;
        }

        uint32_t pHa[8], pHb[8], pLa[8], pLb[8];
        float ps0 = 0.f, ps1 = 0.f;
#pragma unroll
        for (int nj = 0; nj < 8; nj++) {
            float p0 = __expf(sacc[nj][0] - nm0);
            float p1 = __expf(sacc[nj][1] - nm0);
            float p2 = __expf(sacc[nj][2] - nm1);
            float p3 = __expf(sacc[nj][3] - nm1);
            ps0 += p0 + p1;
            ps1 += p2 + p3;
            pHa[nj] = pack_hi(p0, p1);  pLa[nj] = pack_lo(p0, p1, pHa[nj]);
            pHb[nj] = pack_hi(p2, p3);  pLb[nj] = pack_lo(p2, p3, pHb[nj]);
        }
        l0 += ps0;
        l1 += ps1;

        // ---- O += P V ----
#pragma unroll
        for (int kk = 0; kk < 4; kk++) {
            uint32_t aH[4] = { pHa[2 * kk], pHb[2 * kk], pHa[2 * kk + 1], pHb[2 * kk + 1] };
            uint32_t aL[4] = { pLa[2 * kk], pLb[2 * kk], pLa[2 * kk + 1], pLb[2 * kk + 1] };
#pragma unroll
            for (int njp = 0; njp < 8; njp += 2) {
                const uint32_t rowb =
                    (uint32_t)((kk * 16 + (lane & 15)) * 144
                               + (njp + ((lane >> 4) & 1)) * 16);
                uint32_t vh[2][2], vl[2][2];
                LDMX4T(vh[0][0], vh[0][1], vh[1][0], vh[1][1], bVh + rowb);
                LDMX4T(vl[0][0], vl[0][1], vl[1][0], vl[1][1], bVl + rowb);
                MMA16816(oacc[njp],     aH, vh[0]);
                MMA16816(oacc[njp],     aL, vh[0]);
                MMA16816(oacc[njp],     aH, vl[0]);
                MMA16816(oacc[njp + 1], aH, vh[1]);
                MMA16816(oacc[njp + 1], aL, vh[1]);
                MMA16816(oacc[njp + 1], aH, vl[1]);
            }
        }
    }

    // ---- finalize: write output pre-split ----
    l0 += __shfl_xor_sync(0xffffffffu, l0, 1);
    l0 += __shfl_xor_sync(0xffffffffu, l0, 2);
    l1 += __shfl_xor_sync(0xffffffffu, l1, 1);
    l1 += __shfl_xor_sync(0xffffffffu, l1, 2);
    const float rl0 = 1.f / l0;
    const float rl1 = 1.f / l1;

    __nv_bfloat16* Ahb = g_ah + qoff;
    __nv_bfloat16* Alb = g_al + qoff;
#pragma unroll
    for (int nj = 0; nj < 8; nj++) {
        const int colb = nj * 8 + (lane & 3) * 2;
        float x0 = oacc[nj][0] * rl0, y0 = oacc[nj][1] * rl0;
        float x1 = oacc[nj][2] * rl1, y1 = oacc[nj][3] * rl1;
        uint32_t h0 = pack_hi(x0, y0);
        uint32_t h1 = pack_hi(x1, y1);
        *(uint32_t*)(Ahb + (size_t)r0 * H_ + colb)       = h0;
        *(uint32_t*)(Ahb + (size_t)(r0 + 8) * H_ + colb) = h1;
        *(uint32_t*)(Alb + (size_t)r0 * H_ + colb)       = pack_lo(x0, y0, h0);
        *(uint32_t*)(Alb + (size_t)(r0 + 8) * H_ + colb) = pack_lo(x1, y1, h1);
    }
}

// ---------------------------------------------------------------------------
extern "C" void kernel_launch(void* const* d_in, const int* in_sizes, int n_in,
                              void* d_out, int out_size)
{
    const float* query = (const float*)d_in[0];
    const float* key   = (const float*)d_in[1];
    const float* value = (const float*)d_in[2];
    const int*   mask  = (const int*)d_in[3];

    const int wb = (n_in >= 13) ? 5 : 4;
    const float* Wq = (const float*)d_in[wb + 0];
    const float* bq = (const float*)d_in[wb + 1];
    const float* Wk = (const float*)d_in[wb + 2];
    const float* bk = (const float*)d_in[wb + 3];
    const float* Wv = (const float*)d_in[wb + 4];
    const float* bv = (const float*)d_in[wb + 5];
    const float* Wo = (const float*)d_in[wb + 6];
    const float* bo = (const float*)d_in[wb + 7];
    float* out = (float*)d_out;

    __nv_bfloat16 *xqh, *xql, *xkh, *xkl, *xvh, *xvl;
    __nv_bfloat16 *wqh, *wql, *wkh, *wkl, *wvh, *wvl, *woh, *wol;
    cudaGetSymbolAddress((void**)&xqh, g_xqh); cudaGetSymbolAddress((void**)&xql, g_xql);
    cudaGetSymbolAddress((void**)&xkh, g_xkh); cudaGetSymbolAddress((void**)&xkl, g_xkl);
    cudaGetSymbolAddress((void**)&xvh, g_xvh); cudaGetSymbolAddress((void**)&xvl, g_xvl);
    cudaGetSymbolAddress((void**)&wqh, g_wqh); cudaGetSymbolAddress((void**)&wql, g_wql);
    cudaGetSymbolAddress((void**)&wkh, g_wkh); cudaGetSymbolAddress((void**)&wkl, g_wkl);
    cudaGetSymbolAddress((void**)&wvh, g_wvh); cudaGetSymbolAddress((void**)&wvl, g_wvl);
    cudaGetSymbolAddress((void**)&woh, g_woh); cudaGetSymbolAddress((void**)&wol, g_wol);

    cudaFuncSetAttribute(qkv_hl,    cudaFuncAttributeMaxDynamicSharedMemorySize, GEMM_SMEM);
    cudaFuncSetAttribute(gemm_o_hl, cudaFuncAttributeMaxDynamicSharedMemorySize, GEMM_SMEM);
    cudaFuncSetAttribute(attn_tc,   cudaFuncAttributeMaxDynamicSharedMemorySize, ATTN_SMEM);

    const int nBig8 = NBIG / 8;        // 1M uint4 outputs
    const int nWt8  = H_ * H_ / 8;     // 128K
    conv_hl<<<4096, 256>>>(query, xqh, xql, nBig8);
    conv_hl<<<4096, 256>>>(key,   xkh, xkl, nBig8);
    conv_hl<<<4096, 256>>>(value, xvh, xvl, nBig8);
    conv_hl<<<512, 256>>>(Wq, wqh, wql, nWt8);
    conv_hl<<<512, 256>>>(Wk, wkh, wkl, nWt8);
    conv_hl<<<512, 256>>>(Wv, wvh, wvl, nWt8);
    conv_hl<<<512, 256>>>(Wo, woh, wol, nWt8);

    dim3 qkvgrid(H_ / 128, MROWS / 128, 3);  // (8, 64, 3)
    qkv_hl<<<qkvgrid, 256, GEMM_SMEM>>>(bq, bk, bv);

    dim3 agrid(S_ / 128, NH_, B_);           // (8, 16, 8)
    attn_tc<<<agrid, 256, ATTN_SMEM>>>(mask);

    dim3 ggrid(H_ / 128, MROWS / 128);       // (8, 64)
    gemm_o_hl<<<ggrid, 256, GEMM_SMEM>>>(bo, out);
}